// round 8
// baseline (speedup 1.0000x reference)
#include <cuda_runtime.h>

// S5 associative scan, single-pass decoupled lookback (windowed), float4.
//   (A_i,Bu_i)*(A_j,Bu_j) = (A_j*A_i, A_j*Bu_i + Bu_j)
// out[0:T*D] = A_scan, out[T*D:2*T*D] = Bu_scan.
//
// One block = one 16-row chunk. 256 threads = 4 row-groups x 64 channel-quads.
// Upsweep keeps local inclusive scans in SMEM; 64 threads publish per-quad
// block aggregates, run windowed lookback over predecessor chunks, publish
// inclusive; all threads then apply the prefix and stream outputs.
// Inputs are read ONCE: total DRAM traffic 512MB (vs 768MB for 3-pass).

#define TT  131072
#define DD  256
#define RR  16               // rows per chunk
#define NC  (TT / RR)        // 8192 chunks (= blocks)
#define NQ  64               // float4 channel-quads per row
#define RPT 4                // rows per thread
#define NG  4                // row-groups per block
#define LBW 8                // lookback window

// Scratch (static device arrays — allocation rules). ~34MB, L2-resident.
__device__ float4 g_aggA[NC * NQ];
__device__ float4 g_aggS[NC * NQ];
__device__ float4 g_incA[NC * NQ];
__device__ float4 g_incS[NC * NQ];
__device__ int    g_flag[NC * NQ];   // 0=none, 1=aggregate, 2=inclusive

__device__ __forceinline__ int ld_acq(const int* p) {
    int v;
    asm volatile("ld.global.acquire.gpu.b32 %0, [%1];" : "=r"(v) : "l"(p) : "memory");
    return v;
}
__device__ __forceinline__ void st_rel(int* p, int v) {
    asm volatile("st.global.release.gpu.b32 [%0], %1;" :: "l"(p), "r"(v) : "memory");
}
__device__ __forceinline__ float4 ld_cg4(const float4* p) {
    float4 v;
    asm volatile("ld.global.cg.v4.f32 {%0,%1,%2,%3}, [%4];"
                 : "=f"(v.x), "=f"(v.y), "=f"(v.z), "=f"(v.w) : "l"(p) : "memory");
    return v;
}
__device__ __forceinline__ void st_cg4(float4* p, float4 v) {
    asm volatile("st.global.cg.v4.f32 [%0], {%1,%2,%3,%4};"
                 :: "l"(p), "f"(v.x), "f"(v.y), "f"(v.z), "f"(v.w) : "memory");
}

// absorb EARLIER segment x into running LATER combination r:
//   r' = (rA*xA, rA*xS + rS)
#define ABSORB_EARLIER(rA, rS, xa, xs)                              \
    do {                                                            \
        rS.x = fmaf(rA.x, xs.x, rS.x); rS.y = fmaf(rA.y, xs.y, rS.y); \
        rS.z = fmaf(rA.z, xs.z, rS.z); rS.w = fmaf(rA.w, xs.w, rS.w); \
        rA.x *= xa.x; rA.y *= xa.y; rA.z *= xa.z; rA.w *= xa.w;     \
    } while (0)

// apply LATER segment x on top of running prefix P:  P' = (xA*PA, xA*PS + xS)
#define APPLY_LATER(PA, PS, xa, xs)                                 \
    do {                                                            \
        PS.x = fmaf(xa.x, PS.x, xs.x); PS.y = fmaf(xa.y, PS.y, xs.y); \
        PS.z = fmaf(xa.z, PS.z, xs.z); PS.w = fmaf(xa.w, PS.w, xs.w); \
        PA.x *= xa.x; PA.y *= xa.y; PA.z *= xa.z; PA.w *= xa.w;     \
    } while (0)

__global__ void s5_init() {
    const int i = blockIdx.x * blockDim.x + threadIdx.x;
    if (i < NC * NQ) g_flag[i] = 0;
}

__global__ __launch_bounds__(256, 4) void s5_scan(const float4* __restrict__ A4,
                                                  const float4* __restrict__ Bu4,
                                                  float4* __restrict__ outA4,
                                                  float4* __restrict__ outS4) {
    __shared__ float4 shA[RR][NQ];     // local inclusive cumA
    __shared__ float4 shS[RR][NQ];     // local inclusive S
    __shared__ float4 shEA[NQ], shES[NQ];

    const int c = blockIdx.x;
    const int g = threadIdx.x >> 6;    // row-group 0..3
    const int t = threadIdx.x & 63;    // channel-quad
    const size_t base = ((size_t)c * RR + g * RPT) * NQ + t;

    // ---- upsweep: 4 rows per thread, local scans to smem ----
    float4 aA = make_float4(1.f, 1.f, 1.f, 1.f);
    float4 s  = make_float4(0.f, 0.f, 0.f, 0.f);
#pragma unroll
    for (int i = 0; i < RPT; ++i) {
        const float4 a  = __ldcs(A4 + base + (size_t)i * NQ);
        const float4 bu = __ldcs(Bu4 + base + (size_t)i * NQ);
        aA.x *= a.x; aA.y *= a.y; aA.z *= a.z; aA.w *= a.w;
        s.x = fmaf(a.x, s.x, bu.x);
        s.y = fmaf(a.y, s.y, bu.y);
        s.z = fmaf(a.z, s.z, bu.z);
        s.w = fmaf(a.w, s.w, bu.w);
        shA[g * RPT + i][t] = aA;
        shS[g * RPT + i][t] = s;
    }
    __syncthreads();

    // ---- 64 threads: block aggregate, publish, lookback, publish inclusive --
    if (threadIdx.x < 64) {
        // block aggregate for this quad = combine group aggs (rows 3,7,11,15)
        float4 bA = shA[RPT - 1][t];
        float4 bS = shS[RPT - 1][t];
#pragma unroll
        for (int gg = 1; gg < NG; ++gg) {
            const float4 xa = shA[gg * RPT + RPT - 1][t];
            const float4 xs = shS[gg * RPT + RPT - 1][t];
            APPLY_LATER(bA, bS, xa, xs);
        }

        const int slot = c * NQ + t;
        float4 eA = make_float4(1.f, 1.f, 1.f, 1.f);
        float4 eS = make_float4(0.f, 0.f, 0.f, 0.f);

        if (c == 0) {
            st_cg4(&g_incA[slot], bA);
            st_cg4(&g_incS[slot], bS);
            st_rel(&g_flag[slot], 2);
        } else {
            // publish aggregate (payload then flag, same thread: release orders)
            st_cg4(&g_aggA[slot], bA);
            st_cg4(&g_aggS[slot], bS);
            st_rel(&g_flag[slot], 1);

            // windowed lookback: absorb up to LBW predecessors per roundtrip
            float4 rA = make_float4(1.f, 1.f, 1.f, 1.f);
            float4 rS = make_float4(0.f, 0.f, 0.f, 0.f);
            int p = c - 1;
            for (;;) {
                int f0;
                do { f0 = ld_acq(&g_flag[p * NQ + t]); } while (f0 == 0);
                int f[LBW];
                f[0] = f0;
                const int n = (p + 1 < LBW) ? (p + 1) : LBW;
#pragma unroll
                for (int j = 1; j < LBW; ++j)
                    f[j] = (j < n) ? ld_acq(&g_flag[(p - j) * NQ + t]) : 0;
                int m = 0, k2 = -1;
#pragma unroll
                for (int j = 0; j < LBW; ++j) {
                    if (k2 >= 0 || f[j] == 0) break;
                    ++m;
                    if (f[j] == 2) k2 = j;
                }
                // absorb m predecessors in descending-chunk order
                for (int j = 0; j < m; ++j) {
                    const int ps_ = (p - j) * NQ + t;
                    float4 xa, xs;
                    if (j == k2) { xa = ld_cg4(&g_incA[ps_]); xs = ld_cg4(&g_incS[ps_]); }
                    else         { xa = ld_cg4(&g_aggA[ps_]); xs = ld_cg4(&g_aggS[ps_]); }
                    ABSORB_EARLIER(rA, rS, xa, xs);
                }
                if (k2 >= 0) { eA = rA; eS = rS; break; }
                p -= m;
            }

            // publish inclusive = blockAgg applied after exclusive prefix
            float4 iA = eA, iS = eS;
            APPLY_LATER(iA, iS, bA, bS);
            st_cg4(&g_incA[slot], iA);
            st_cg4(&g_incS[slot], iS);
            st_rel(&g_flag[slot], 2);
        }
        shEA[t] = eA;
        shES[t] = eS;
    }
    __syncthreads();

    // ---- downsweep: prefix for this thread's group, write outputs ----
    float4 EA = shEA[t];
    float4 ES = shES[t];
    for (int gg = 0; gg < g; ++gg) {                 // earlier groups in block
        const float4 xa = shA[gg * RPT + RPT - 1][t];
        const float4 xs = shS[gg * RPT + RPT - 1][t];
        APPLY_LATER(EA, ES, xa, xs);
    }
#pragma unroll
    for (int i = 0; i < RPT; ++i) {
        const float4 lA = shA[g * RPT + i][t];
        const float4 lS = shS[g * RPT + i][t];
        float4 oA, oS;
        oA.x = lA.x * EA.x; oA.y = lA.y * EA.y;
        oA.z = lA.z * EA.z; oA.w = lA.w * EA.w;
        oS.x = fmaf(lA.x, ES.x, lS.x); oS.y = fmaf(lA.y, ES.y, lS.y);
        oS.z = fmaf(lA.z, ES.z, lS.z); oS.w = fmaf(lA.w, ES.w, lS.w);
        __stcs(outA4 + base + (size_t)i * NQ, oA);
        __stcs(outS4 + base + (size_t)i * NQ, oS);
    }
}

extern "C" void kernel_launch(void* const* d_in, const int* in_sizes, int n_in,
                              void* d_out, int out_size) {
    const float4* A4  = (const float4*)d_in[0];
    const float4* Bu4 = (const float4*)d_in[1];
    float4* outA4 = (float4*)d_out;
    float4* outS4 = (float4*)((float*)d_out + (size_t)TT * DD);

    s5_init<<<(NC * NQ + 255) / 256, 256>>>();
    s5_scan<<<NC, 256>>>(A4, Bu4, outA4, outS4);
}

// round 9
// speedup vs baseline: 2.2041x; 2.2041x over previous
#include <cuda_runtime.h>

// S5 associative scan: (A_i,Bu_i)*(A_j,Bu_j) = (A_j*A_i, A_j*Bu_i + Bu_j)
// Per channel d:  cumA_t = A_t * cumA_{t-1},   S_t = A_t*S_{t-1} + Bu_t
// out[0:T*D] = A_scan, out[T*D:2*T*D] = Bu_scan.
//
// 3-pass chunked scan, float4-vectorized, 4 chunks per 256-thread block.
// L2 carry-over optimization: pass1 reads inputs with DEFAULT caching (tail
// ~120MB of inputs stays L2-resident), pass3 walks chunks in REVERSE order so
// its first blocks hit those lines; pass3 output stores are streaming (.cs)
// to avoid evicting the input leftovers.

#define TT 131072
#define DD 256
#define GG 4096              // time chunks
#define LL (TT / GG)         // 32 rows per chunk
#define V4 (DD / 4)          // 64 float4 per row
#define CPB 4                // chunks per block (passes 1 & 3)
#define P2T (GG / 4)         // 1024 threads in pass2

// Scratch (static device arrays — allocation rules).
__device__ float g_aggA[GG * DD];    // [c][d] chunk-major
__device__ float g_aggS[GG * DD];
__device__ float g_prefA[GG * DD];   // [c][d] chunk-major (exclusive prefix)
__device__ float g_prefS[GG * DD];

// ---------------- pass 1: per-chunk aggregates ----------------
__global__ __launch_bounds__(V4 * CPB) void s5_pass1(const float4* __restrict__ A4,
                                                     const float4* __restrict__ Bu4) {
    const int sub = threadIdx.x >> 6;       // chunk within block
    const int t   = threadIdx.x & 63;       // float4 lane (channels 4t..4t+3)
    const int c   = blockIdx.x * CPB + sub;
    const size_t base = (size_t)c * LL * V4 + t;

    float4 aA = make_float4(1.f, 1.f, 1.f, 1.f);
    float4 s  = make_float4(0.f, 0.f, 0.f, 0.f);
#pragma unroll
    for (int i = 0; i < LL; ++i) {
        const float4 a  = A4[base + (size_t)i * V4];    // default caching: seed L2
        const float4 bu = Bu4[base + (size_t)i * V4];
        aA.x *= a.x; aA.y *= a.y; aA.z *= a.z; aA.w *= a.w;
        s.x = fmaf(a.x, s.x, bu.x);
        s.y = fmaf(a.y, s.y, bu.y);
        s.z = fmaf(a.z, s.z, bu.z);
        s.w = fmaf(a.w, s.w, bu.w);
    }
    ((float4*)g_aggA)[c * V4 + t] = aA;     // coalesced, stays in L2 for pass2
    ((float4*)g_aggS)[c * V4 + t] = s;
}

// ---------------- pass 2: cross-chunk scan (one block per channel) ----------
__global__ __launch_bounds__(P2T) void s5_pass2() {
    __shared__ float shA[P2T];
    __shared__ float shS[P2T];
    const int d = blockIdx.x;
    const int c = threadIdx.x;              // owns chunks 4c..4c+3

    // serial combine of 4 consecutive chunk aggregates (keep raw copies)
    float la[4], ls[4];
    float vA = 1.f, vS = 0.f;
#pragma unroll
    for (int j = 0; j < 4; ++j) {
        const float a = g_aggA[(c * 4 + j) * DD + d];
        const float s = g_aggS[(c * 4 + j) * DD + d];
        la[j] = a; ls[j] = s;
        vS = fmaf(a, vS, s);
        vA = vA * a;
    }
    shA[c] = vA;
    shS[c] = vS;
    __syncthreads();

    // Kogge-Stone inclusive scan over 1024 thread-aggregates
#pragma unroll
    for (int off = 1; off < P2T; off <<= 1) {
        float pA = 0.f, pS = 0.f;
        const bool valid = (c >= off);
        if (valid) { pA = shA[c - off]; pS = shS[c - off]; }
        __syncthreads();
        if (valid) {
            vS = fmaf(vA, pS, vS);
            vA = vA * pA;
            shA[c] = vA;
            shS[c] = vS;
        }
        __syncthreads();
    }

    // exclusive prefix entering this thread's 4 chunks
    float eA = (c == 0) ? 1.f : shA[c - 1];
    float eS = (c == 0) ? 0.f : shS[c - 1];
#pragma unroll
    for (int j = 0; j < 4; ++j) {
        g_prefA[(c * 4 + j) * DD + d] = eA;
        g_prefS[(c * 4 + j) * DD + d] = eS;
        eS = fmaf(la[j], eS, ls[j]);
        eA = eA * la[j];
    }
}

// ---------------- pass 3: rescan with prefix, write outputs -----------------
// Chunks processed in REVERSE order: first pass3 blocks read the input lines
// pass1 touched last (still L2-resident).
__global__ __launch_bounds__(V4 * CPB) void s5_pass3(const float4* __restrict__ A4,
                                                     const float4* __restrict__ Bu4,
                                                     float4* __restrict__ outA4,
                                                     float4* __restrict__ outS4) {
    const int sub = threadIdx.x >> 6;
    const int t   = threadIdx.x & 63;
    const int c   = (GG - 1) - (blockIdx.x * CPB + sub);   // reverse mapping
    const size_t base = (size_t)c * LL * V4 + t;

    float4 aA = ((const float4*)g_prefA)[c * V4 + t];   // coalesced (L2 hit)
    float4 s  = ((const float4*)g_prefS)[c * V4 + t];

#pragma unroll
    for (int i = 0; i < LL; ++i) {
        const size_t idx = base + (size_t)i * V4;
        const float4 a  = A4[idx];          // default caching: exploit L2 leftovers
        const float4 bu = Bu4[idx];
        aA.x *= a.x; aA.y *= a.y; aA.z *= a.z; aA.w *= a.w;
        s.x = fmaf(a.x, s.x, bu.x);
        s.y = fmaf(a.y, s.y, bu.y);
        s.z = fmaf(a.z, s.z, bu.z);
        s.w = fmaf(a.w, s.w, bu.w);
        __stcs(outA4 + idx, aA);            // streaming: don't evict inputs
        __stcs(outS4 + idx, s);
    }
}

extern "C" void kernel_launch(void* const* d_in, const int* in_sizes, int n_in,
                              void* d_out, int out_size) {
    const float4* A4  = (const float4*)d_in[0];
    const float4* Bu4 = (const float4*)d_in[1];
    float4* outA4 = (float4*)d_out;
    float4* outS4 = (float4*)((float*)d_out + (size_t)TT * DD);

    s5_pass1<<<GG / CPB, V4 * CPB>>>(A4, Bu4);
    s5_pass2<<<DD, P2T>>>();
    s5_pass3<<<GG / CPB, V4 * CPB>>>(A4, Bu4, outA4, outS4);
}